// round 2
// baseline (speedup 1.0000x reference)
#include <cuda_runtime.h>
#include <math.h>

#define N_TOK 16384
#define D_MOD 1024
#define H_N   16
#define HK    64
#define M_F   256
#define FF_D  4096
#define S_LEN 4096
#define B_N   4
#define PHI_SCALE 0.35355339059327373f   // 64^-0.25
#define RSQRT_M  0.0625f                 // 1/sqrt(256)

// ---------------- scratch (device globals; allocation-free) ----------------
__device__ float g_q   [N_TOK * D_MOD];
__device__ float g_k   [N_TOK * D_MOD];
__device__ float g_v   [N_TOK * D_MOD];
__device__ float g_pq  [64 * S_LEN * M_F];   // [b*h][s][m]
__device__ float g_pk  [64 * S_LEN * M_F];
__device__ float g_kv  [64 * M_F * HK];
__device__ float g_z   [64 * M_F];
__device__ float g_attn[N_TOK * D_MOD];
__device__ float g_y   [N_TOK * D_MOD];
__device__ float g_x1  [N_TOK * D_MOD];
__device__ float g_act [N_TOK * FF_D];

// ---------------- generic tiled fp32 GEMM: C = A @ B (+epilogue) ----------
// A: [Nrows x Kd] row-major, B: [Kd x NC] row-major, C: [Nrows x NC]
// EPI: 0 = none, 1 = +res, 2 = gelu(x+bias), 3 = +bias+res
template<int EPI>
__global__ __launch_bounds__(256, 2)
void gemm128(const float* __restrict__ A, const float* __restrict__ B,
             const float* __restrict__ bias, const float* __restrict__ R,
             float* __restrict__ C, int Kd, int NC)
{
    __shared__ float As[16][128];
    __shared__ float Bs[16][128];

    int tid = threadIdx.x;
    int r0 = blockIdx.y * 128;
    int c0 = blockIdx.x * 128;
    int tx = tid & 15, ty = tid >> 4;

    // A-load mapping: 2 threads per row, 8 cols each
    int arow = tid >> 1;
    int ac   = (tid & 1) * 8;
    const float* Aptr = A + (size_t)(r0 + arow) * Kd + ac;

    // B-load mapping: 16 threads per row, 2 float4 each
    int brow = tid >> 4;
    int bc   = (tid & 15) * 4;
    const float* Bptr = B + (size_t)brow * NC + c0 + bc;

    float c[8][8];
    #pragma unroll
    for (int i = 0; i < 8; i++)
        #pragma unroll
        for (int j = 0; j < 8; j++) c[i][j] = 0.f;

    float4 pa0 = *(const float4*)(Aptr);
    float4 pa1 = *(const float4*)(Aptr + 4);
    float4 pb0 = *(const float4*)(Bptr);
    float4 pb1 = *(const float4*)(Bptr + 64);

    int nk = Kd >> 4;
    for (int kt = 0; kt < nk; kt++) {
        As[ac+0][arow] = pa0.x; As[ac+1][arow] = pa0.y;
        As[ac+2][arow] = pa0.z; As[ac+3][arow] = pa0.w;
        As[ac+4][arow] = pa1.x; As[ac+5][arow] = pa1.y;
        As[ac+6][arow] = pa1.z; As[ac+7][arow] = pa1.w;
        *(float4*)&Bs[brow][bc]      = pb0;
        *(float4*)&Bs[brow][bc + 64] = pb1;
        __syncthreads();

        if (kt + 1 < nk) {
            const float* An = Aptr + (size_t)(kt + 1) * 16;
            const float* Bn = Bptr + (size_t)(kt + 1) * 16 * NC;
            pa0 = *(const float4*)(An);
            pa1 = *(const float4*)(An + 4);
            pb0 = *(const float4*)(Bn);
            pb1 = *(const float4*)(Bn + 64);
        }

        #pragma unroll
        for (int kk = 0; kk < 16; kk++) {
            float4 a0 = *(const float4*)&As[kk][ty * 8];
            float4 a1 = *(const float4*)&As[kk][ty * 8 + 4];
            float4 b0 = *(const float4*)&Bs[kk][tx * 8];
            float4 b1 = *(const float4*)&Bs[kk][tx * 8 + 4];
            float av[8] = {a0.x,a0.y,a0.z,a0.w,a1.x,a1.y,a1.z,a1.w};
            float bv[8] = {b0.x,b0.y,b0.z,b0.w,b1.x,b1.y,b1.z,b1.w};
            #pragma unroll
            for (int i = 0; i < 8; i++)
                #pragma unroll
                for (int j = 0; j < 8; j++)
                    c[i][j] += av[i] * bv[j];
        }
        __syncthreads();
    }

    #pragma unroll
    for (int i = 0; i < 8; i++) {
        int row = r0 + ty * 8 + i;
        size_t base = (size_t)row * NC + c0 + tx * 8;
        float buf[8];
        #pragma unroll
        for (int j = 0; j < 8; j++) {
            float val = c[i][j];
            int col = c0 + tx * 8 + j;
            if (EPI == 1) {
                val += R[base + j];
            } else if (EPI == 2) {
                val += bias[col];
                val = 0.5f * val * (1.0f + erff(val * 0.70710678118654752f));
            } else if (EPI == 3) {
                val += bias[col] + R[base + j];
            }
            buf[j] = val;
        }
        *(float4*)(C + base)     = make_float4(buf[0], buf[1], buf[2], buf[3]);
        *(float4*)(C + base + 4) = make_float4(buf[4], buf[5], buf[6], buf[7]);
    }
}

// ---------------- FAVOR+ feature map ----------------
// src: [N_TOK][D_MOD] holding per-head rows (cols h*64..h*64+63)
// dst: [b*H+h][s][m]
__global__ __launch_bounds__(256)
void phi_kernel(const float* __restrict__ src, const float* __restrict__ omega,
                float* __restrict__ dst)
{
    int tid = threadIdx.x;           // = m
    float om[64];
    #pragma unroll
    for (int kk = 0; kk < 64; kk++) om[kk] = omega[tid * 64 + kk];

    __shared__ float u_s[64];
    __shared__ float wmax[8], wsum[8];

    for (int r = blockIdx.x; r < N_TOK * H_N; r += gridDim.x) {
        int n = r >> 4, h = r & 15;
        if (tid < 16) {
            float4 t = *(const float4*)(src + (size_t)n * D_MOD + h * 64 + tid * 4);
            t.x *= PHI_SCALE; t.y *= PHI_SCALE; t.z *= PHI_SCALE; t.w *= PHI_SCALE;
            *(float4*)&u_s[tid * 4] = t;
        }
        __syncthreads();

        float acc = 0.f;
        #pragma unroll
        for (int k4 = 0; k4 < 16; k4++) {
            float4 u4 = *(const float4*)&u_s[k4 * 4];
            acc += om[k4*4+0]*u4.x + om[k4*4+1]*u4.y + om[k4*4+2]*u4.z + om[k4*4+3]*u4.w;
        }
        float sqp = (tid < 64) ? u_s[tid] * u_s[tid] : 0.f;

        float mx = acc;
        #pragma unroll
        for (int o = 16; o; o >>= 1) {
            mx  = fmaxf(mx, __shfl_xor_sync(0xFFFFFFFFu, mx, o));
            sqp += __shfl_xor_sync(0xFFFFFFFFu, sqp, o);
        }
        if ((tid & 31) == 0) { wmax[tid >> 5] = mx; wsum[tid >> 5] = sqp; }
        __syncthreads();

        float stab = wmax[0], ssum = wsum[0];
        #pragma unroll
        for (int w = 1; w < 8; w++) {
            stab = fmaxf(stab, wmax[w]);
            ssum += wsum[w];
        }
        float val = __expf(acc - 0.5f * ssum - stab) * RSQRT_M + 1e-6f;

        int b = n >> 12, s = n & 4095;
        dst[(((size_t)(b * H_N + h)) * S_LEN + s) * M_F + tid] = val;
        __syncthreads();
    }
}

// ---------------- kv[m][k] = sum_s pk[s][m] v[s][k];  z[m] = sum_s pk[s][m] ----
__global__ __launch_bounds__(256)
void kv_kernel(const float* __restrict__ pk, const float* __restrict__ v,
               float* __restrict__ kv, float* __restrict__ z)
{
    int bh = blockIdx.x >> 2;
    int chunk = blockIdx.x & 3;
    int b = bh >> 4, h = bh & 15;
    int tid = threadIdx.x;           // = m

    __shared__ float pk_s[8][256];
    __shared__ float v_s[8][64];

    float acc[64];
    #pragma unroll
    for (int i = 0; i < 64; i++) acc[i] = 0.f;
    float az = 0.f;

    const float* pkb = pk + ((size_t)bh * S_LEN + chunk * 1024) * M_F;
    const float* vb  = v + ((size_t)(b * S_LEN + chunk * 1024)) * D_MOD + h * 64;

    for (int s0 = 0; s0 < 1024; s0 += 8) {
        #pragma unroll
        for (int i = 0; i < 8; i++)
            pk_s[i][tid] = pkb[(size_t)(s0 + i) * M_F + tid];
        if (tid < 128) {
            int i = tid >> 4, c4 = tid & 15;
            *(float4*)&v_s[i][c4 * 4] =
                *(const float4*)(vb + (size_t)(s0 + i) * D_MOD + c4 * 4);
        }
        __syncthreads();
        #pragma unroll
        for (int i = 0; i < 8; i++) {
            float p = pk_s[i][tid];
            az += p;
            #pragma unroll
            for (int k4 = 0; k4 < 16; k4++) {
                float4 vv = *(const float4*)&v_s[i][k4 * 4];
                acc[k4*4+0] += p * vv.x;
                acc[k4*4+1] += p * vv.y;
                acc[k4*4+2] += p * vv.z;
                acc[k4*4+3] += p * vv.w;
            }
        }
        __syncthreads();
    }

    float* kvp = kv + (size_t)bh * (M_F * HK) + tid * 64;
    #pragma unroll
    for (int k = 0; k < 64; k++) atomicAdd(kvp + k, acc[k]);
    atomicAdd(z + bh * M_F + tid, az);
}

// ---------------- num/den + normalize + head-concat ----------------
__global__ __launch_bounds__(256)
void numden_kernel(const float* __restrict__ pq, const float* __restrict__ kvg,
                   const float* __restrict__ zg, float* __restrict__ attn)
{
    extern __shared__ float sm[];
    float* kv_s = sm;            // 16384
    float* z_s  = sm + 16384;    // 256
    float* pq_s = sm + 16640;    // 1024

    int bh = blockIdx.x >> 4;
    int chunk = blockIdx.x & 15;
    int b = bh >> 4, h = bh & 15;
    int tid = threadIdx.x;

    const float4* kvsrc = (const float4*)(kvg + (size_t)bh * (M_F * HK));
    #pragma unroll
    for (int i = 0; i < 16; i++)
        ((float4*)kv_s)[tid + 256 * i] = kvsrc[tid + 256 * i];
    if (tid < 64)
        ((float4*)z_s)[tid] = ((const float4*)(zg + bh * M_F))[tid];
    __syncthreads();

    int r = tid >> 6, k = tid & 63;
    const float* pqb = pq + ((size_t)bh * S_LEN + chunk * 256) * M_F;

    for (int sg = 0; sg < 64; sg++) {
        ((float4*)pq_s)[tid] =
            *(const float4*)(pqb + (size_t)(sg * 4 + (tid >> 6)) * M_F + (tid & 63) * 4);
        __syncthreads();

        float num = 0.f, den = 0.f;
        const float* prow = pq_s + r * 256;
        #pragma unroll 8
        for (int m4 = 0; m4 < 64; m4++) {
            float4 p  = ((const float4*)prow)[m4];
            float4 zz = ((const float4*)z_s)[m4];
            int mb = m4 * 4;
            num += p.x * kv_s[(mb+0)*64 + k] + p.y * kv_s[(mb+1)*64 + k]
                 + p.z * kv_s[(mb+2)*64 + k] + p.w * kv_s[(mb+3)*64 + k];
            den += p.x * zz.x + p.y * zz.y + p.z * zz.z + p.w * zz.w;
        }
        int s = chunk * 256 + sg * 4 + r;
        attn[((size_t)(b * S_LEN + s)) * D_MOD + h * 64 + k] = num / den;
        __syncthreads();
    }
}

// ---------------- LayerNorm (residual already folded by GEMM epilogue) -----
__global__ void ln_kernel(const float* __restrict__ X, const float* __restrict__ g,
                          const float* __restrict__ bv, float* __restrict__ out)
{
    int row = blockIdx.x, tid = threadIdx.x;
    float4 v = ((const float4*)(X + (size_t)row * D_MOD))[tid];
    float s = v.x + v.y + v.z + v.w;
    __shared__ float ws[8];
    #pragma unroll
    for (int o = 16; o; o >>= 1) s += __shfl_xor_sync(0xFFFFFFFFu, s, o);
    if ((tid & 31) == 0) ws[tid >> 5] = s;
    __syncthreads();
    float tot = 0.f;
    #pragma unroll
    for (int w = 0; w < 8; w++) tot += ws[w];
    float mu = tot * (1.f / 1024.f);
    float dx = v.x - mu, dy = v.y - mu, dz = v.z - mu, dw = v.w - mu;
    float sq = dx*dx + dy*dy + dz*dz + dw*dw;
    __syncthreads();
    #pragma unroll
    for (int o = 16; o; o >>= 1) sq += __shfl_xor_sync(0xFFFFFFFFu, sq, o);
    if ((tid & 31) == 0) ws[tid >> 5] = sq;
    __syncthreads();
    float tot2 = 0.f;
    #pragma unroll
    for (int w = 0; w < 8; w++) tot2 += ws[w];
    float rs = rsqrtf(tot2 * (1.f / 1024.f) + 1e-6f);
    float4 gg = ((const float4*)g)[tid];
    float4 bb = ((const float4*)bv)[tid];
    float4 o4 = make_float4(dx*rs*gg.x + bb.x, dy*rs*gg.y + bb.y,
                            dz*rs*gg.z + bb.z, dw*rs*gg.w + bb.w);
    ((float4*)(out + (size_t)row * D_MOD))[tid] = o4;
}

__global__ void zero_kernel(float* p, int n)
{
    int i = blockIdx.x * blockDim.x + threadIdx.x;
    if (i < n) p[i] = 0.f;
}

// ---------------- orchestration ----------------
extern "C" void kernel_launch(void* const* d_in, const int* in_sizes, int n_in,
                              void* d_out, int out_size)
{
    const float* x     = (const float*)d_in[0];
    const float* wq    = (const float*)d_in[1];
    const float* wk    = (const float*)d_in[2];
    const float* wv    = (const float*)d_in[3];
    const float* wo    = (const float*)d_in[4];
    const float* omega = (const float*)d_in[5];
    const float* ln1g  = (const float*)d_in[6];
    const float* ln1b  = (const float*)d_in[7];
    const float* w1    = (const float*)d_in[8];
    const float* b1    = (const float*)d_in[9];
    const float* w2    = (const float*)d_in[10];
    const float* b2    = (const float*)d_in[11];
    const float* ln2g  = (const float*)d_in[12];
    const float* ln2b  = (const float*)d_in[13];
    float* out = (float*)d_out;

    float *q, *k, *v, *pq, *pk, *kv, *z, *attn, *y, *x1, *act;
    cudaGetSymbolAddress((void**)&q,    g_q);
    cudaGetSymbolAddress((void**)&k,    g_k);
    cudaGetSymbolAddress((void**)&v,    g_v);
    cudaGetSymbolAddress((void**)&pq,   g_pq);
    cudaGetSymbolAddress((void**)&pk,   g_pk);
    cudaGetSymbolAddress((void**)&kv,   g_kv);
    cudaGetSymbolAddress((void**)&z,    g_z);
    cudaGetSymbolAddress((void**)&attn, g_attn);
    cudaGetSymbolAddress((void**)&y,    g_y);
    cudaGetSymbolAddress((void**)&x1,   g_x1);
    cudaGetSymbolAddress((void**)&act,  g_act);

    cudaFuncSetAttribute(numden_kernel,
                         cudaFuncAttributeMaxDynamicSharedMemorySize, 70656);

    dim3 gD(D_MOD / 128, N_TOK / 128);   // (8, 128)
    dim3 gF(FF_D / 128, N_TOK / 128);    // (32, 128)

    // QKV projections
    gemm128<0><<<gD, 256>>>(x, wq, nullptr, nullptr, q, D_MOD, D_MOD);
    gemm128<0><<<gD, 256>>>(x, wk, nullptr, nullptr, k, D_MOD, D_MOD);
    gemm128<0><<<gD, 256>>>(x, wv, nullptr, nullptr, v, D_MOD, D_MOD);

    // FAVOR+ features
    phi_kernel<<<2048, 256>>>(q, omega, pq);
    phi_kernel<<<2048, 256>>>(k, omega, pk);

    // kv / z aggregation
    zero_kernel<<<(64 * M_F * HK + 255) / 256, 256>>>(kv, 64 * M_F * HK);
    zero_kernel<<<(64 * M_F + 255) / 256, 256>>>(z, 64 * M_F);
    kv_kernel<<<256, 256>>>(pk, v, kv, z);

    // num/den + normalize
    numden_kernel<<<1024, 256, 70656>>>(pq, kv, z, attn);

    // output projection + residual, LN1
    gemm128<1><<<gD, 256>>>(attn, wo, nullptr, x, y, D_MOD, D_MOD);
    ln_kernel<<<N_TOK, 256>>>(y, ln1g, ln1b, x1);

    // FFN
    gemm128<2><<<gF, 256>>>(x1, w1, b1, nullptr, act, D_MOD, FF_D);
    gemm128<3><<<gD, 256>>>(act, w2, b2, x1, y, FF_D, D_MOD);
    ln_kernel<<<N_TOK, 256>>>(y, ln2g, ln2b, out);
}

// round 4
// speedup vs baseline: 1.5695x; 1.5695x over previous
#include <cuda_runtime.h>
#include <math.h>

#define N_TOK 16384
#define D_MOD 1024
#define H_N   16
#define HK    64
#define M_F   256
#define FF_D  4096
#define S_LEN 4096
#define PHI_SCALE 0.35355339059327373f   // 64^-0.25
#define RSQRT_M  0.0625f                 // 1/sqrt(256)

// ---------------- scratch (device globals; allocation-free) ----------------
__device__ float g_q   [N_TOK * D_MOD];
__device__ float g_k   [N_TOK * D_MOD];
__device__ float g_v   [N_TOK * D_MOD];
__device__ float g_pq  [64 * S_LEN * M_F];
__device__ float g_pk  [64 * S_LEN * M_F];
__device__ float g_kv  [64 * M_F * HK];
__device__ float g_z   [64 * M_F];
__device__ float g_attn[N_TOK * D_MOD];
__device__ float g_y   [N_TOK * D_MOD];
__device__ float g_x1  [N_TOK * D_MOD];
__device__ float g_act [N_TOK * FF_D];
__device__ float g_wqT [D_MOD * D_MOD];
__device__ float g_wkT [D_MOD * D_MOD];
__device__ float g_wvT [D_MOD * D_MOD];
__device__ float g_woT [D_MOD * D_MOD];
__device__ float g_w1T [D_MOD * FF_D];
__device__ float g_w2T [D_MOD * FF_D];

__device__ __forceinline__ unsigned f2tf32(float f) {
    unsigned u;
    asm("cvt.rn.tf32.f32 %0, %1;" : "=r"(u) : "f"(f));
    return u;
}

__device__ __forceinline__ void mma_tf32(float* d, const unsigned* a, const unsigned* b) {
    asm volatile(
        "mma.sync.aligned.m16n8k8.row.col.f32.tf32.tf32.f32 "
        "{%0,%1,%2,%3}, {%4,%5,%6,%7}, {%8,%9}, {%0,%1,%2,%3};"
        : "+f"(d[0]), "+f"(d[1]), "+f"(d[2]), "+f"(d[3])
        : "r"(a[0]), "r"(a[1]), "r"(a[2]), "r"(a[3]), "r"(b[0]), "r"(b[1]));
}

// ---------------- warp-MMA tf32 GEMM: C[M,N] = A[M,Kd] @ BT[N,Kd]^T ----------
// SMEM fragment layout:
//  A_s[m_tile(8)][kstep(4)][reg(4)][lane(32)]  -> 4096 u32 per buffer
//  B_s[n_tile(16)][kstep(4)][reg(2)][lane(32)] -> 4096 u32 per buffer
// EPI: 0 none, 1 +res, 2 gelu(x+bias), 3 +bias+res
#define SM_DYN 67584   // stage (128*132*4) aliases the two 32KB buffers

template<int EPI>
__global__ __launch_bounds__(256, 2)
void tc_gemm(const float* __restrict__ A, const float* __restrict__ BT,
             const float* __restrict__ bias, const float* __restrict__ R,
             float* __restrict__ C, int Kd, int NC)
{
    extern __shared__ char sm[];
    int tid = threadIdx.x, wid = tid >> 5, lane = tid & 31;
    int r0 = blockIdx.y * 128, c0 = blockIdx.x * 128;
    int wm = wid & 1, wn = wid >> 1;        // warp tile: rows wm*64, cols wn*32

    const float* Ab = A + (size_t)r0 * Kd;
    const float* Bb = BT + (size_t)c0 * Kd;

    float acc[4][4][4];
    #pragma unroll
    for (int mi = 0; mi < 4; mi++)
        #pragma unroll
        for (int ni = 0; ni < 4; ni++)
            #pragma unroll
            for (int j = 0; j < 4; j++) acc[mi][ni][j] = 0.f;

    // per-thread fill mapping: u = tid + 256*i ; row = u>>3, j = u&7 (float4 col)
    int nk = Kd >> 5;
    float4 pa[4], pb[4];
    #pragma unroll
    for (int i = 0; i < 4; i++) {
        int u = tid + 256 * i, row = u >> 3, j = u & 7;
        pa[i] = *(const float4*)(Ab + (size_t)row * Kd + j * 4);
        pb[i] = *(const float4*)(Bb + (size_t)row * Kd + j * 4);
    }

    for (int c = 0; c < nk; c++) {
        int p = c & 1;
        unsigned* As = (unsigned*)sm + p * 8192;
        unsigned* Bs = (unsigned*)sm + p * 8192 + 4096;

        // store prefetched chunk into fragment-ordered smem (tf32 RN rounding)
        #pragma unroll
        for (int i = 0; i < 4; i++) {
            int u = tid + 256 * i, row = u >> 3, j = u & 7;
            int ks = j >> 1;
            // A: m_tile = row>>4, r16 = row&15 ; reg = (r16>=8) + 2*(j&1)
            int r16 = row & 15;
            unsigned aoff = (unsigned)((row >> 4) * 512 + ks * 128 +
                                       (((r16 >> 3) + 2 * (j & 1)) * 32) + (r16 & 7) * 4);
            *(uint4*)(As + aoff) = make_uint4(f2tf32(pa[i].x), f2tf32(pa[i].y),
                                              f2tf32(pa[i].z), f2tf32(pa[i].w));
            // B: n_tile = row>>3, n8 = row&7 ; reg = j&1
            unsigned boff = (unsigned)((row >> 3) * 256 + ks * 64 +
                                       ((j & 1) * 32) + (row & 7) * 4);
            *(uint4*)(Bs + boff) = make_uint4(f2tf32(pb[i].x), f2tf32(pb[i].y),
                                              f2tf32(pb[i].z), f2tf32(pb[i].w));
        }
        __syncthreads();

        if (c + 1 < nk) {
            const float* An = Ab + (c + 1) * 32;
            const float* Bn = Bb + (c + 1) * 32;
            #pragma unroll
            for (int i = 0; i < 4; i++) {
                int u = tid + 256 * i, row = u >> 3, j = u & 7;
                pa[i] = *(const float4*)(An + (size_t)row * Kd + j * 4);
                pb[i] = *(const float4*)(Bn + (size_t)row * Kd + j * 4);
            }
        }

        #pragma unroll
        for (int ks = 0; ks < 4; ks++) {
            unsigned afr[4][4], bfr[4][2];
            #pragma unroll
            for (int mi = 0; mi < 4; mi++) {
                const unsigned* ap = As + (wm * 4 + mi) * 512 + ks * 128 + lane;
                afr[mi][0] = ap[0];  afr[mi][1] = ap[32];
                afr[mi][2] = ap[64]; afr[mi][3] = ap[96];
            }
            #pragma unroll
            for (int ni = 0; ni < 4; ni++) {
                const unsigned* bp = Bs + (wn * 4 + ni) * 256 + ks * 64 + lane;
                bfr[ni][0] = bp[0]; bfr[ni][1] = bp[32];
            }
            #pragma unroll
            for (int mi = 0; mi < 4; mi++)
                #pragma unroll
                for (int ni = 0; ni < 4; ni++)
                    mma_tf32(acc[mi][ni], afr[mi], bfr[ni]);
        }
        __syncthreads();
    }

    // epilogue: acc frags -> SMEM stage (stride 132) -> coalesced STG
    float* stage = (float*)sm;
    #pragma unroll
    for (int mi = 0; mi < 4; mi++)
        #pragma unroll
        for (int ni = 0; ni < 4; ni++) {
            int row = wm * 64 + mi * 16 + (lane >> 2);
            int col = wn * 32 + ni * 8 + (lane & 3) * 2;
            *(float2*)(stage + row * 132 + col) =
                make_float2(acc[mi][ni][0], acc[mi][ni][1]);
            *(float2*)(stage + (row + 8) * 132 + col) =
                make_float2(acc[mi][ni][2], acc[mi][ni][3]);
        }
    __syncthreads();

    #pragma unroll
    for (int i = 0; i < 16; i++) {
        int u = tid + 256 * i;
        int row = u >> 5, c4 = u & 31;
        float4 v = *(const float4*)(stage + row * 132 + c4 * 4);
        size_t base = (size_t)(r0 + row) * NC + c0 + c4 * 4;
        float vv[4] = {v.x, v.y, v.z, v.w};
        #pragma unroll
        for (int j = 0; j < 4; j++) {
            int col = c0 + c4 * 4 + j;
            if (EPI == 1) vv[j] += R[base + j];
            else if (EPI == 2) {
                float t = vv[j] + bias[col];
                vv[j] = 0.5f * t * (1.0f + erff(t * 0.70710678118654752f));
            } else if (EPI == 3) vv[j] += bias[col] + R[base + j];
        }
        *(float4*)(C + base) = make_float4(vv[0], vv[1], vv[2], vv[3]);
    }
}

// ---------------- transpose: out[C][R] = in[R][C]^T ----------------
__global__ void transpose_k(const float* __restrict__ in, float* __restrict__ out,
                            int R, int Cc)
{
    __shared__ float t[32][33];
    int x = blockIdx.x * 32 + threadIdx.x;
    int y = blockIdx.y * 32 + threadIdx.y;
    #pragma unroll
    for (int j = 0; j < 4; j++)
        t[threadIdx.y + j * 8][threadIdx.x] = in[(size_t)(y + j * 8) * Cc + x];
    __syncthreads();
    int ox = blockIdx.y * 32 + threadIdx.x;
    int oy = blockIdx.x * 32 + threadIdx.y;
    #pragma unroll
    for (int j = 0; j < 4; j++)
        out[(size_t)(oy + j * 8) * R + ox] = t[threadIdx.x][threadIdx.y + j * 8];
}

// ---------------- FAVOR+ feature map (warp per 4 rows) ----------------
__global__ __launch_bounds__(256)
void phi_kernel(const float* __restrict__ src, const float* __restrict__ omega,
                float* __restrict__ dst)
{
    __shared__ float om[64 * 256];   // [k][m]
    int tid = threadIdx.x, wid = tid >> 5, lane = tid & 31;
    for (int i = tid; i < 16384; i += 256) {
        int m = i >> 6, k = i & 63;
        om[k * 256 + m] = omega[i];
    }
    __syncthreads();

    int rowBase = blockIdx.x * 128 + wid * 16;
    for (int g = 0; g < 4; g++) {
        int r0 = rowBase + g * 4;
        float u0[4], u1[4], sq[4];
        #pragma unroll
        for (int rr = 0; rr < 4; rr++) {
            int r = r0 + rr, n = r >> 4, h = r & 15;
            float2 t = *(const float2*)(src + (size_t)n * D_MOD + h * 64 + lane * 2);
            u0[rr] = t.x * PHI_SCALE;
            u1[rr] = t.y * PHI_SCALE;
            float s = u0[rr] * u0[rr] + u1[rr] * u1[rr];
            #pragma unroll
            for (int o = 16; o; o >>= 1) s += __shfl_xor_sync(0xFFFFFFFFu, s, o);
            sq[rr] = 0.5f * s;
        }
        float acc[4][8];
        #pragma unroll
        for (int rr = 0; rr < 4; rr++)
            #pragma unroll
            for (int j = 0; j < 8; j++) acc[rr][j] = 0.f;

        #pragma unroll 4
        for (int k2 = 0; k2 < 32; k2++) {
            float4 wa0 = *(const float4*)&om[(2 * k2) * 256 + lane * 8];
            float4 wa1 = *(const float4*)&om[(2 * k2) * 256 + lane * 8 + 4];
            float4 wb0 = *(const float4*)&om[(2 * k2 + 1) * 256 + lane * 8];
            float4 wb1 = *(const float4*)&om[(2 * k2 + 1) * 256 + lane * 8 + 4];
            #pragma unroll
            for (int rr = 0; rr < 4; rr++) {
                float ua = __shfl_sync(0xFFFFFFFFu, u0[rr], k2);
                float ub = __shfl_sync(0xFFFFFFFFu, u1[rr], k2);
                acc[rr][0] += ua * wa0.x + ub * wb0.x;
                acc[rr][1] += ua * wa0.y + ub * wb0.y;
                acc[rr][2] += ua * wa0.z + ub * wb0.z;
                acc[rr][3] += ua * wa0.w + ub * wb0.w;
                acc[rr][4] += ua * wa1.x + ub * wb1.x;
                acc[rr][5] += ua * wa1.y + ub * wb1.y;
                acc[rr][6] += ua * wa1.z + ub * wb1.z;
                acc[rr][7] += ua * wa1.w + ub * wb1.w;
            }
        }
        #pragma unroll
        for (int rr = 0; rr < 4; rr++) {
            int r = r0 + rr, n = r >> 4, h = r & 15;
            int b = n >> 12, s = n & 4095;
            float mx = acc[rr][0];
            #pragma unroll
            for (int j = 1; j < 8; j++) mx = fmaxf(mx, acc[rr][j]);
            #pragma unroll
            for (int o = 16; o; o >>= 1) mx = fmaxf(mx, __shfl_xor_sync(0xFFFFFFFFu, mx, o));
            float out[8];
            #pragma unroll
            for (int j = 0; j < 8; j++)
                out[j] = __expf(acc[rr][j] - sq[rr] - mx) * RSQRT_M + 1e-6f;
            float* d = dst + (((size_t)(b * H_N + h)) * S_LEN + s) * M_F + lane * 8;
            *(float4*)(d)     = make_float4(out[0], out[1], out[2], out[3]);
            *(float4*)(d + 4) = make_float4(out[4], out[5], out[6], out[7]);
        }
    }
}

// ---------------- kv[m][k] = sum_s pk[s][m] v[s][k]; z[m] = sum_s pk[s][m] ----
__global__ __launch_bounds__(256)
void kv_kernel(const float* __restrict__ pk, const float* __restrict__ v,
               float* __restrict__ kv, float* __restrict__ z)
{
    int bh = blockIdx.x >> 2;
    int chunk = blockIdx.x & 3;
    int b = bh >> 4, h = bh & 15;
    int tid = threadIdx.x;

    __shared__ float pk_s[8][256];
    __shared__ float v_s[8][64];

    float acc[64];
    #pragma unroll
    for (int i = 0; i < 64; i++) acc[i] = 0.f;
    float az = 0.f;

    const float* pkb = pk + ((size_t)bh * S_LEN + chunk * 1024) * M_F;
    const float* vb  = v + ((size_t)(b * S_LEN + chunk * 1024)) * D_MOD + h * 64;

    for (int s0 = 0; s0 < 1024; s0 += 8) {
        #pragma unroll
        for (int i = 0; i < 8; i++)
            pk_s[i][tid] = pkb[(size_t)(s0 + i) * M_F + tid];
        if (tid < 128) {
            int i = tid >> 4, c4 = tid & 15;
            *(float4*)&v_s[i][c4 * 4] =
                *(const float4*)(vb + (size_t)(s0 + i) * D_MOD + c4 * 4);
        }
        __syncthreads();
        #pragma unroll
        for (int i = 0; i < 8; i++) {
            float p = pk_s[i][tid];
            az += p;
            #pragma unroll
            for (int k4 = 0; k4 < 16; k4++) {
                float4 vv = *(const float4*)&v_s[i][k4 * 4];
                acc[k4*4+0] += p * vv.x;
                acc[k4*4+1] += p * vv.y;
                acc[k4*4+2] += p * vv.z;
                acc[k4*4+3] += p * vv.w;
            }
        }
        __syncthreads();
    }

    float* kvp = kv + (size_t)bh * (M_F * HK) + tid * 64;
    #pragma unroll
    for (int k = 0; k < 64; k++) atomicAdd(kvp + k, acc[k]);
    atomicAdd(z + bh * M_F + tid, az);
}

// ---------------- num/den + normalize + head-concat ----------------
__global__ __launch_bounds__(256)
void numden_kernel(const float* __restrict__ pq, const float* __restrict__ kvg,
                   const float* __restrict__ zg, float* __restrict__ attn)
{
    extern __shared__ float smf[];
    float* kv_s = smf;
    float* z_s  = smf + 16384;
    float* pq_s = smf + 16640;

    int bh = blockIdx.x >> 4;
    int chunk = blockIdx.x & 15;
    int b = bh >> 4, h = bh & 15;
    int tid = threadIdx.x;

    const float4* kvsrc = (const float4*)(kvg + (size_t)bh * (M_F * HK));
    #pragma unroll
    for (int i = 0; i < 16; i++)
        ((float4*)kv_s)[tid + 256 * i] = kvsrc[tid + 256 * i];
    if (tid < 64)
        ((float4*)z_s)[tid] = ((const float4*)(zg + bh * M_F))[tid];
    __syncthreads();

    int r = tid >> 6, k = tid & 63;
    const float* pqb = pq + ((size_t)bh * S_LEN + chunk * 256) * M_F;

    for (int sg = 0; sg < 64; sg++) {
        ((float4*)pq_s)[tid] =
            *(const float4*)(pqb + (size_t)(sg * 4 + (tid >> 6)) * M_F + (tid & 63) * 4);
        __syncthreads();

        float num = 0.f, den = 0.f;
        const float* prow = pq_s + r * 256;
        #pragma unroll 8
        for (int m4 = 0; m4 < 64; m4++) {
            float4 p  = ((const float4*)prow)[m4];
            float4 zz = ((const float4*)z_s)[m4];
            int mb = m4 * 4;
            num += p.x * kv_s[(mb+0)*64 + k] + p.y * kv_s[(mb+1)*64 + k]
                 + p.z * kv_s[(mb+2)*64 + k] + p.w * kv_s[(mb+3)*64 + k];
            den += p.x * zz.x + p.y * zz.y + p.z * zz.z + p.w * zz.w;
        }
        int s = chunk * 256 + sg * 4 + r;
        attn[((size_t)(b * S_LEN + s)) * D_MOD + h * 64 + k] = num / den;
        __syncthreads();
    }
}

// ---------------- LayerNorm ----------------
__global__ void ln_kernel(const float* __restrict__ X, const float* __restrict__ g,
                          const float* __restrict__ bv, float* __restrict__ out)
{
    int row = blockIdx.x, tid = threadIdx.x;
    float4 v = ((const float4*)(X + (size_t)row * D_MOD))[tid];
    float s = v.x + v.y + v.z + v.w;
    __shared__ float ws[8];
    #pragma unroll
    for (int o = 16; o; o >>= 1) s += __shfl_xor_sync(0xFFFFFFFFu, s, o);
    if ((tid & 31) == 0) ws[tid >> 5] = s;
    __syncthreads();
    float tot = 0.f;
    #pragma unroll
    for (int w = 0; w < 8; w++) tot += ws[w];
    float mu = tot * (1.f / 1024.f);
    float dx = v.x - mu, dy = v.y - mu, dz = v.z - mu, dw = v.w - mu;
    float sqv = dx*dx + dy*dy + dz*dz + dw*dw;
    __syncthreads();
    #pragma unroll
    for (int o = 16; o; o >>= 1) sqv += __shfl_xor_sync(0xFFFFFFFFu, sqv, o);
    if ((tid & 31) == 0) ws[tid >> 5] = sqv;
    __syncthreads();
    float tot2 = 0.f;
    #pragma unroll
    for (int w = 0; w < 8; w++) tot2 += ws[w];
    float rs = rsqrtf(tot2 * (1.f / 1024.f) + 1e-6f);
    float4 gg = ((const float4*)g)[tid];
    float4 bb = ((const float4*)bv)[tid];
    ((float4*)(out + (size_t)row * D_MOD))[tid] = make_float4(
        dx*rs*gg.x + bb.x, dy*rs*gg.y + bb.y, dz*rs*gg.z + bb.z, dw*rs*gg.w + bb.w);
}

__global__ void zero_kernel(float* p, int n)
{
    int i = blockIdx.x * blockDim.x + threadIdx.x;
    if (i < n) p[i] = 0.f;
}

// ---------------- orchestration ----------------
extern "C" void kernel_launch(void* const* d_in, const int* in_sizes, int n_in,
                              void* d_out, int out_size)
{
    const float* x     = (const float*)d_in[0];
    const float* wq    = (const float*)d_in[1];
    const float* wk    = (const float*)d_in[2];
    const float* wv    = (const float*)d_in[3];
    const float* wo    = (const float*)d_in[4];
    const float* omega = (const float*)d_in[5];
    const float* ln1g  = (const float*)d_in[6];
    const float* ln1b  = (const float*)d_in[7];
    const float* w1    = (const float*)d_in[8];
    const float* b1    = (const float*)d_in[9];
    const float* w2    = (const float*)d_in[10];
    const float* b2    = (const float*)d_in[11];
    const float* ln2g  = (const float*)d_in[12];
    const float* ln2b  = (const float*)d_in[13];
    float* out = (float*)d_out;

    float *q, *k, *v, *pq, *pk, *kv, *z, *attn, *y, *x1, *act;
    float *wqT, *wkT, *wvT, *woT, *w1T, *w2T;
    cudaGetSymbolAddress((void**)&q,    g_q);
    cudaGetSymbolAddress((void**)&k,    g_k);
    cudaGetSymbolAddress((void**)&v,    g_v);
    cudaGetSymbolAddress((void**)&pq,   g_pq);
    cudaGetSymbolAddress((void**)&pk,   g_pk);
    cudaGetSymbolAddress((void**)&kv,   g_kv);
    cudaGetSymbolAddress((void**)&z,    g_z);
    cudaGetSymbolAddress((void**)&attn, g_attn);
    cudaGetSymbolAddress((void**)&y,    g_y);
    cudaGetSymbolAddress((void**)&x1,   g_x1);
    cudaGetSymbolAddress((void**)&act,  g_act);
    cudaGetSymbolAddress((void**)&wqT,  g_wqT);
    cudaGetSymbolAddress((void**)&wkT,  g_wkT);
    cudaGetSymbolAddress((void**)&wvT,  g_wvT);
    cudaGetSymbolAddress((void**)&woT,  g_woT);
    cudaGetSymbolAddress((void**)&w1T,  g_w1T);
    cudaGetSymbolAddress((void**)&w2T,  g_w2T);

    cudaFuncSetAttribute(numden_kernel, cudaFuncAttributeMaxDynamicSharedMemorySize, 70656);
    cudaFuncSetAttribute(tc_gemm<0>, cudaFuncAttributeMaxDynamicSharedMemorySize, SM_DYN);
    cudaFuncSetAttribute(tc_gemm<1>, cudaFuncAttributeMaxDynamicSharedMemorySize, SM_DYN);
    cudaFuncSetAttribute(tc_gemm<2>, cudaFuncAttributeMaxDynamicSharedMemorySize, SM_DYN);
    cudaFuncSetAttribute(tc_gemm<3>, cudaFuncAttributeMaxDynamicSharedMemorySize, SM_DYN);

    dim3 tb(32, 8);
    transpose_k<<<dim3(32, 32),   tb>>>(wq, wqT, 1024, 1024);
    transpose_k<<<dim3(32, 32),   tb>>>(wk, wkT, 1024, 1024);
    transpose_k<<<dim3(32, 32),   tb>>>(wv, wvT, 1024, 1024);
    transpose_k<<<dim3(32, 32),   tb>>>(wo, woT, 1024, 1024);
    transpose_k<<<dim3(128, 32),  tb>>>(w1, w1T, 1024, 4096);
    transpose_k<<<dim3(32, 128),  tb>>>(w2, w2T, 4096, 1024);

    dim3 gD(D_MOD / 128, N_TOK / 128);   // (8, 128)
    dim3 gF(FF_D / 128, N_TOK / 128);    // (32, 128)

    tc_gemm<0><<<gD, 256, SM_DYN>>>(x, wqT, nullptr, nullptr, q, D_MOD, D_MOD);
    tc_gemm<0><<<gD, 256, SM_DYN>>>(x, wkT, nullptr, nullptr, k, D_MOD, D_MOD);
    tc_gemm<0><<<gD, 256, SM_DYN>>>(x, wvT, nullptr, nullptr, v, D_MOD, D_MOD);

    phi_kernel<<<2048, 256>>>(q, omega, pq);
    phi_kernel<<<2048, 256>>>(k, omega, pk);

    zero_kernel<<<(64 * M_F * HK + 255) / 256, 256>>>(kv, 64 * M_F * HK);
    zero_kernel<<<(64 * M_F + 255) / 256, 256>>>(z, 64 * M_F);
    kv_kernel<<<256, 256>>>(pk, v, kv, z);

    numden_kernel<<<1024, 256, 70656>>>(pq, kv, z, attn);

    tc_gemm<1><<<gD, 256, SM_DYN>>>(attn, woT, nullptr, x, y, D_MOD, D_MOD);
    ln_kernel<<<N_TOK, 256>>>(y, ln1g, ln1b, x1);

    tc_gemm<2><<<gF, 256, SM_DYN>>>(x1, w1T, b1, nullptr, act, D_MOD, FF_D);
    tc_gemm<3><<<gD, 256, SM_DYN>>>(act, w2T, b2, x1, y, FF_D, D_MOD);
    ln_kernel<<<N_TOK, 256>>>(y, ln2g, ln2b, out);
}

// round 5
// speedup vs baseline: 2.4532x; 1.5630x over previous
#include <cuda_runtime.h>
#include <math.h>

#define N_TOK 16384
#define D_MOD 1024
#define H_N   16
#define HK    64
#define M_F   256
#define FF_D  4096
#define S_LEN 4096
#define PHI_SCALE 0.35355339059327373f   // 64^-0.25
#define RSQRT_M  0.0625f                 // 1/sqrt(256)

// ---------------- scratch (device globals; allocation-free) ----------------
__device__ float g_q   [N_TOK * D_MOD];
__device__ float g_k   [N_TOK * D_MOD];
__device__ float g_v   [N_TOK * D_MOD];
__device__ float g_pq  [64 * S_LEN * M_F];
__device__ float g_pk  [64 * S_LEN * M_F];
__device__ float g_kv  [64 * M_F * HK];
__device__ float g_z   [64 * M_F];
__device__ float g_attn[N_TOK * D_MOD];
__device__ float g_y   [N_TOK * D_MOD];
__device__ float g_x1  [N_TOK * D_MOD];
__device__ float g_act [N_TOK * FF_D];
__device__ float g_wqT [D_MOD * D_MOD];
__device__ float g_wkT [D_MOD * D_MOD];
__device__ float g_wvT [D_MOD * D_MOD];
__device__ float g_woT [D_MOD * D_MOD];
__device__ float g_w1T [D_MOD * FF_D];
__device__ float g_w2T [D_MOD * FF_D];

__device__ __forceinline__ unsigned smem_u32(const void* p) {
    unsigned a;
    asm("{ .reg .u64 t; cvta.to.shared.u64 t, %1; cvt.u32.u64 %0, t; }" : "=r"(a) : "l"(p));
    return a;
}

__device__ __forceinline__ void mma_tf32(float* d, const unsigned* a, const unsigned* b) {
    asm volatile(
        "mma.sync.aligned.m16n8k8.row.col.f32.tf32.tf32.f32 "
        "{%0,%1,%2,%3}, {%4,%5,%6,%7}, {%8,%9}, {%0,%1,%2,%3};"
        : "+f"(d[0]), "+f"(d[1]), "+f"(d[2]), "+f"(d[3])
        : "r"(a[0]), "r"(a[1]), "r"(a[2]), "r"(a[3]), "r"(b[0]), "r"(b[1]));
}

#define CP16(dst, src) \
    asm volatile("cp.async.ca.shared.global [%0], [%1], 16;" :: "r"(dst), "l"(src))
#define CP_COMMIT() asm volatile("cp.async.commit_group;" ::: "memory")
#define CP_WAIT1()  asm volatile("cp.async.wait_group 1;" ::: "memory")
#define CP_WAIT0()  asm volatile("cp.async.wait_group 0;" ::: "memory")

// ---------------- warp-MMA tf32 GEMM: C[M,N] = A[M,Kd] @ BT[N,Kd]^T ----------
// 128x128 CTA tile, 8 warps (warp tile 64x32), K-chunk 32.
// SMEM: 2 stages x (A[128][36] + B[128][36]) floats, stride 36 => bank-conflict-free.
// EPI: 0 none, 1 +res, 2 gelu(x+bias), 3 +bias+res
#define TSTR   36
#define ABYTES (128 * TSTR * 4)          // 18432
#define STAGEB (2 * ABYTES)              // 36864
#define SM_DYN (2 * STAGEB)              // 73728

template<int EPI>
__global__ __launch_bounds__(256, 2)
void tc_gemm(const float* __restrict__ A, const float* __restrict__ BT,
             const float* __restrict__ bias, const float* __restrict__ R,
             float* __restrict__ C, int Kd, int NC)
{
    extern __shared__ char sm[];
    unsigned smu = smem_u32(sm);
    int tid = threadIdx.x, wid = tid >> 5, lane = tid & 31;
    int r0 = blockIdx.y * 128, c0 = blockIdx.x * 128;
    int wm = wid & 1, wn = wid >> 1;     // warp tile: rows wm*64, cols wn*32

    const float* Ab = A + (size_t)r0 * Kd;
    const float* Bb = BT + (size_t)c0 * Kd;

    // per-thread copy mapping: u = tid + 256*i ; row = u>>3, seg = u&7 (16B)
    int crow[4], cseg[4];
    unsigned cdst[4];
    #pragma unroll
    for (int i = 0; i < 4; i++) {
        int u = tid + 256 * i;
        crow[i] = u >> 3; cseg[i] = u & 7;
        cdst[i] = smu + (unsigned)(crow[i] * TSTR + cseg[i] * 4) * 4;
    }

    float acc[4][4][4];
    #pragma unroll
    for (int mi = 0; mi < 4; mi++)
        #pragma unroll
        for (int ni = 0; ni < 4; ni++)
            #pragma unroll
            for (int j = 0; j < 4; j++) acc[mi][ni][j] = 0.f;

    int nk = Kd >> 5;

    // prologue: stage 0 and stage 1 loads in flight
    #pragma unroll
    for (int s = 0; s < 2; s++) {
        if (s < nk) {
            const float* Ac = Ab + s * 32;
            const float* Bc = Bb + s * 32;
            unsigned so = s * STAGEB;
            #pragma unroll
            for (int i = 0; i < 4; i++) {
                CP16(cdst[i] + so,          Ac + (size_t)crow[i] * Kd + cseg[i] * 4);
                CP16(cdst[i] + so + ABYTES, Bc + (size_t)crow[i] * Kd + cseg[i] * 4);
            }
        }
        CP_COMMIT();
    }

    // warp fragment base offsets (floats)
    int kfrag = lane & 3;
    int mrow = wm * 64 + (lane >> 2);
    int nrow = wn * 32 + (lane >> 2);

    for (int c = 0; c < nk; c++) {
        int p = c & 1;
        CP_WAIT1();
        __syncthreads();

        const unsigned* As = (const unsigned*)(sm + p * STAGEB);
        const unsigned* Bs = (const unsigned*)(sm + p * STAGEB + ABYTES);

        #pragma unroll
        for (int ks = 0; ks < 4; ks++) {
            int kk = ks * 8 + kfrag;
            unsigned afr[4][4], bfr[4][2];
            #pragma unroll
            for (int mi = 0; mi < 4; mi++) {
                const unsigned* ap = As + (mrow + mi * 16) * TSTR + kk;
                afr[mi][0] = ap[0];
                afr[mi][1] = ap[8 * TSTR];
                afr[mi][2] = ap[4];
                afr[mi][3] = ap[8 * TSTR + 4];
            }
            #pragma unroll
            for (int ni = 0; ni < 4; ni++) {
                const unsigned* bp = Bs + (nrow + ni * 8) * TSTR + kk;
                bfr[ni][0] = bp[0];
                bfr[ni][1] = bp[4];
            }
            #pragma unroll
            for (int mi = 0; mi < 4; mi++)
                #pragma unroll
                for (int ni = 0; ni < 4; ni++)
                    mma_tf32(acc[mi][ni], afr[mi], bfr[ni]);
        }
        __syncthreads();

        if (c + 2 < nk) {
            const float* Ac = Ab + (c + 2) * 32;
            const float* Bc = Bb + (c + 2) * 32;
            unsigned so = p * STAGEB;
            #pragma unroll
            for (int i = 0; i < 4; i++) {
                CP16(cdst[i] + so,          Ac + (size_t)crow[i] * Kd + cseg[i] * 4);
                CP16(cdst[i] + so + ABYTES, Bc + (size_t)crow[i] * Kd + cseg[i] * 4);
            }
        }
        CP_COMMIT();
    }
    CP_WAIT0();
    __syncthreads();

    // epilogue: acc frags -> SMEM stage (stride 132) -> coalesced STG
    float* stage = (float*)sm;
    #pragma unroll
    for (int mi = 0; mi < 4; mi++)
        #pragma unroll
        for (int ni = 0; ni < 4; ni++) {
            int row = wm * 64 + mi * 16 + (lane >> 2);
            int col = wn * 32 + ni * 8 + (lane & 3) * 2;
            *(float2*)(stage + row * 132 + col) =
                make_float2(acc[mi][ni][0], acc[mi][ni][1]);
            *(float2*)(stage + (row + 8) * 132 + col) =
                make_float2(acc[mi][ni][2], acc[mi][ni][3]);
        }
    __syncthreads();

    #pragma unroll
    for (int i = 0; i < 16; i++) {
        int u = tid + 256 * i;
        int row = u >> 5, c4 = u & 31;
        float4 v = *(const float4*)(stage + row * 132 + c4 * 4);
        size_t base = (size_t)(r0 + row) * NC + c0 + c4 * 4;
        float vv[4] = {v.x, v.y, v.z, v.w};
        #pragma unroll
        for (int j = 0; j < 4; j++) {
            int col = c0 + c4 * 4 + j;
            if (EPI == 1) vv[j] += R[base + j];
            else if (EPI == 2) {
                float t = vv[j] + bias[col];
                vv[j] = 0.5f * t * (1.0f + erff(t * 0.70710678118654752f));
            } else if (EPI == 3) vv[j] += bias[col] + R[base + j];
        }
        *(float4*)(C + base) = make_float4(vv[0], vv[1], vv[2], vv[3]);
    }
}

// ---------------- transpose: out[C][R] = in[R][C]^T ----------------
__global__ void transpose_k(const float* __restrict__ in, float* __restrict__ out,
                            int R, int Cc)
{
    __shared__ float t[32][33];
    int x = blockIdx.x * 32 + threadIdx.x;
    int y = blockIdx.y * 32 + threadIdx.y;
    #pragma unroll
    for (int j = 0; j < 4; j++)
        t[threadIdx.y + j * 8][threadIdx.x] = in[(size_t)(y + j * 8) * Cc + x];
    __syncthreads();
    int ox = blockIdx.y * 32 + threadIdx.x;
    int oy = blockIdx.x * 32 + threadIdx.y;
    #pragma unroll
    for (int j = 0; j < 4; j++)
        out[(size_t)(oy + j * 8) * R + ox] = t[threadIdx.x][threadIdx.y + j * 8];
}

// ---------------- FAVOR+ feature map (warp per 4 rows) ----------------
__global__ __launch_bounds__(256)
void phi_kernel(const float* __restrict__ src, const float* __restrict__ omega,
                float* __restrict__ dst)
{
    __shared__ float om[64 * 256];   // [k][m]
    int tid = threadIdx.x, wid = tid >> 5, lane = tid & 31;
    for (int i = tid; i < 16384; i += 256) {
        int m = i >> 6, k = i & 63;
        om[k * 256 + m] = omega[i];
    }
    __syncthreads();

    int rowBase = blockIdx.x * 128 + wid * 16;
    for (int g = 0; g < 4; g++) {
        int r0 = rowBase + g * 4;
        float u0[4], u1[4], sq[4];
        #pragma unroll
        for (int rr = 0; rr < 4; rr++) {
            int r = r0 + rr, n = r >> 4, h = r & 15;
            float2 t = *(const float2*)(src + (size_t)n * D_MOD + h * 64 + lane * 2);
            u0[rr] = t.x * PHI_SCALE;
            u1[rr] = t.y * PHI_SCALE;
            float s = u0[rr] * u0[rr] + u1[rr] * u1[rr];
            #pragma unroll
            for (int o = 16; o; o >>= 1) s += __shfl_xor_sync(0xFFFFFFFFu, s, o);
            sq[rr] = 0.5f * s;
        }
        float acc[4][8];
        #pragma unroll
        for (int rr = 0; rr < 4; rr++)
            #pragma unroll
            for (int j = 0; j < 8; j++) acc[rr][j] = 0.f;

        #pragma unroll 4
        for (int k2 = 0; k2 < 32; k2++) {
            float4 wa0 = *(const float4*)&om[(2 * k2) * 256 + lane * 8];
            float4 wa1 = *(const float4*)&om[(2 * k2) * 256 + lane * 8 + 4];
            float4 wb0 = *(const float4*)&om[(2 * k2 + 1) * 256 + lane * 8];
            float4 wb1 = *(const float4*)&om[(2 * k2 + 1) * 256 + lane * 8 + 4];
            #pragma unroll
            for (int rr = 0; rr < 4; rr++) {
                float ua = __shfl_sync(0xFFFFFFFFu, u0[rr], k2);
                float ub = __shfl_sync(0xFFFFFFFFu, u1[rr], k2);
                acc[rr][0] += ua * wa0.x + ub * wb0.x;
                acc[rr][1] += ua * wa0.y + ub * wb0.y;
                acc[rr][2] += ua * wa0.z + ub * wb0.z;
                acc[rr][3] += ua * wa0.w + ub * wb0.w;
                acc[rr][4] += ua * wa1.x + ub * wb1.x;
                acc[rr][5] += ua * wa1.y + ub * wb1.y;
                acc[rr][6] += ua * wa1.z + ub * wb1.z;
                acc[rr][7] += ua * wa1.w + ub * wb1.w;
            }
        }
        #pragma unroll
        for (int rr = 0; rr < 4; rr++) {
            int r = r0 + rr, n = r >> 4, h = r & 15;
            int b = n >> 12, s = n & 4095;
            float mx = acc[rr][0];
            #pragma unroll
            for (int j = 1; j < 8; j++) mx = fmaxf(mx, acc[rr][j]);
            #pragma unroll
            for (int o = 16; o; o >>= 1) mx = fmaxf(mx, __shfl_xor_sync(0xFFFFFFFFu, mx, o));
            float out[8];
            #pragma unroll
            for (int j = 0; j < 8; j++)
                out[j] = __expf(acc[rr][j] - sq[rr] - mx) * RSQRT_M + 1e-6f;
            float* d = dst + (((size_t)(b * H_N + h)) * S_LEN + s) * M_F + lane * 8;
            *(float4*)(d)     = make_float4(out[0], out[1], out[2], out[3]);
            *(float4*)(d + 4) = make_float4(out[4], out[5], out[6], out[7]);
        }
    }
}

// ---------------- kv[m][k] = sum_s pk[s][m] v[s][k]; z[m] = sum_s pk[s][m] ----
__global__ __launch_bounds__(256)
void kv_kernel(const float* __restrict__ pk, const float* __restrict__ v,
               float* __restrict__ kv, float* __restrict__ z)
{
    int bh = blockIdx.x >> 2;
    int chunk = blockIdx.x & 3;
    int b = bh >> 4, h = bh & 15;
    int tid = threadIdx.x;

    __shared__ float pk_s[8][256];
    __shared__ float v_s[8][64];

    float acc[64];
    #pragma unroll
    for (int i = 0; i < 64; i++) acc[i] = 0.f;
    float az = 0.f;

    const float* pkb = pk + ((size_t)bh * S_LEN + chunk * 1024) * M_F;
    const float* vb  = v + ((size_t)(b * S_LEN + chunk * 1024)) * D_MOD + h * 64;

    for (int s0 = 0; s0 < 1024; s0 += 8) {
        #pragma unroll
        for (int i = 0; i < 8; i++)
            pk_s[i][tid] = pkb[(size_t)(s0 + i) * M_F + tid];
        if (tid < 128) {
            int i = tid >> 4, c4 = tid & 15;
            *(float4*)&v_s[i][c4 * 4] =
                *(const float4*)(vb + (size_t)(s0 + i) * D_MOD + c4 * 4);
        }
        __syncthreads();
        #pragma unroll
        for (int i = 0; i < 8; i++) {
            float p = pk_s[i][tid];
            az += p;
            #pragma unroll
            for (int k4 = 0; k4 < 16; k4++) {
                float4 vv = *(const float4*)&v_s[i][k4 * 4];
                acc[k4*4+0] += p * vv.x;
                acc[k4*4+1] += p * vv.y;
                acc[k4*4+2] += p * vv.z;
                acc[k4*4+3] += p * vv.w;
            }
        }
        __syncthreads();
    }

    float* kvp = kv + (size_t)bh * (M_F * HK) + tid * 64;
    #pragma unroll
    for (int k = 0; k < 64; k++) atomicAdd(kvp + k, acc[k]);
    atomicAdd(z + bh * M_F + tid, az);
}

// ---------------- num/den + normalize + head-concat ----------------
__global__ __launch_bounds__(256)
void numden_kernel(const float* __restrict__ pq, const float* __restrict__ kvg,
                   const float* __restrict__ zg, float* __restrict__ attn)
{
    extern __shared__ float smf[];
    float* kv_s = smf;
    float* z_s  = smf + 16384;
    float* pq_s = smf + 16640;

    int bh = blockIdx.x >> 4;
    int chunk = blockIdx.x & 15;
    int b = bh >> 4, h = bh & 15;
    int tid = threadIdx.x;

    const float4* kvsrc = (const float4*)(kvg + (size_t)bh * (M_F * HK));
    #pragma unroll
    for (int i = 0; i < 16; i++)
        ((float4*)kv_s)[tid + 256 * i] = kvsrc[tid + 256 * i];
    if (tid < 64)
        ((float4*)z_s)[tid] = ((const float4*)(zg + bh * M_F))[tid];
    __syncthreads();

    int r = tid >> 6, k = tid & 63;
    const float* pqb = pq + ((size_t)bh * S_LEN + chunk * 256) * M_F;

    for (int sg = 0; sg < 64; sg++) {
        ((float4*)pq_s)[tid] =
            *(const float4*)(pqb + (size_t)(sg * 4 + (tid >> 6)) * M_F + (tid & 63) * 4);
        __syncthreads();

        float num = 0.f, den = 0.f;
        const float* prow = pq_s + r * 256;
        #pragma unroll 8
        for (int m4 = 0; m4 < 64; m4++) {
            float4 p  = ((const float4*)prow)[m4];
            float4 zz = ((const float4*)z_s)[m4];
            int mb = m4 * 4;
            num += p.x * kv_s[(mb+0)*64 + k] + p.y * kv_s[(mb+1)*64 + k]
                 + p.z * kv_s[(mb+2)*64 + k] + p.w * kv_s[(mb+3)*64 + k];
            den += p.x * zz.x + p.y * zz.y + p.z * zz.z + p.w * zz.w;
        }
        int s = chunk * 256 + sg * 4 + r;
        attn[((size_t)(b * S_LEN + s)) * D_MOD + h * 64 + k] = num / den;
        __syncthreads();
    }
}

// ---------------- LayerNorm ----------------
__global__ void ln_kernel(const float* __restrict__ X, const float* __restrict__ g,
                          const float* __restrict__ bv, float* __restrict__ out)
{
    int row = blockIdx.x, tid = threadIdx.x;
    float4 v = ((const float4*)(X + (size_t)row * D_MOD))[tid];
    float s = v.x + v.y + v.z + v.w;
    __shared__ float ws[8];
    #pragma unroll
    for (int o = 16; o; o >>= 1) s += __shfl_xor_sync(0xFFFFFFFFu, s, o);
    if ((tid & 31) == 0) ws[tid >> 5] = s;
    __syncthreads();
    float tot = 0.f;
    #pragma unroll
    for (int w = 0; w < 8; w++) tot += ws[w];
    float mu = tot * (1.f / 1024.f);
    float dx = v.x - mu, dy = v.y - mu, dz = v.z - mu, dw = v.w - mu;
    float sqv = dx*dx + dy*dy + dz*dz + dw*dw;
    __syncthreads();
    #pragma unroll
    for (int o = 16; o; o >>= 1) sqv += __shfl_xor_sync(0xFFFFFFFFu, sqv, o);
    if ((tid & 31) == 0) ws[tid >> 5] = sqv;
    __syncthreads();
    float tot2 = 0.f;
    #pragma unroll
    for (int w = 0; w < 8; w++) tot2 += ws[w];
    float rs = rsqrtf(tot2 * (1.f / 1024.f) + 1e-6f);
    float4 gg = ((const float4*)g)[tid];
    float4 bb = ((const float4*)bv)[tid];
    ((float4*)(out + (size_t)row * D_MOD))[tid] = make_float4(
        dx*rs*gg.x + bb.x, dy*rs*gg.y + bb.y, dz*rs*gg.z + bb.z, dw*rs*gg.w + bb.w);
}

__global__ void zero_kernel(float* p, int n)
{
    int i = blockIdx.x * blockDim.x + threadIdx.x;
    if (i < n) p[i] = 0.f;
}

// ---------------- orchestration ----------------
extern "C" void kernel_launch(void* const* d_in, const int* in_sizes, int n_in,
                              void* d_out, int out_size)
{
    const float* x     = (const float*)d_in[0];
    const float* wq    = (const float*)d_in[1];
    const float* wk    = (const float*)d_in[2];
    const float* wv    = (const float*)d_in[3];
    const float* wo    = (const float*)d_in[4];
    const float* omega = (const float*)d_in[5];
    const float* ln1g  = (const float*)d_in[6];
    const float* ln1b  = (const float*)d_in[7];
    const float* w1    = (const float*)d_in[8];
    const float* b1    = (const float*)d_in[9];
    const float* w2    = (const float*)d_in[10];
    const float* b2    = (const float*)d_in[11];
    const float* ln2g  = (const float*)d_in[12];
    const float* ln2b  = (const float*)d_in[13];
    float* out = (float*)d_out;

    float *q, *k, *v, *pq, *pk, *kv, *z, *attn, *y, *x1, *act;
    float *wqT, *wkT, *wvT, *woT, *w1T, *w2T;
    cudaGetSymbolAddress((void**)&q,    g_q);
    cudaGetSymbolAddress((void**)&k,    g_k);
    cudaGetSymbolAddress((void**)&v,    g_v);
    cudaGetSymbolAddress((void**)&pq,   g_pq);
    cudaGetSymbolAddress((void**)&pk,   g_pk);
    cudaGetSymbolAddress((void**)&kv,   g_kv);
    cudaGetSymbolAddress((void**)&z,    g_z);
    cudaGetSymbolAddress((void**)&attn, g_attn);
    cudaGetSymbolAddress((void**)&y,    g_y);
    cudaGetSymbolAddress((void**)&x1,   g_x1);
    cudaGetSymbolAddress((void**)&act,  g_act);
    cudaGetSymbolAddress((void**)&wqT,  g_wqT);
    cudaGetSymbolAddress((void**)&wkT,  g_wkT);
    cudaGetSymbolAddress((void**)&wvT,  g_wvT);
    cudaGetSymbolAddress((void**)&woT,  g_woT);
    cudaGetSymbolAddress((void**)&w1T,  g_w1T);
    cudaGetSymbolAddress((void**)&w2T,  g_w2T);

    cudaFuncSetAttribute(numden_kernel, cudaFuncAttributeMaxDynamicSharedMemorySize, 70656);
    cudaFuncSetAttribute(tc_gemm<0>, cudaFuncAttributeMaxDynamicSharedMemorySize, SM_DYN);
    cudaFuncSetAttribute(tc_gemm<1>, cudaFuncAttributeMaxDynamicSharedMemorySize, SM_DYN);
    cudaFuncSetAttribute(tc_gemm<2>, cudaFuncAttributeMaxDynamicSharedMemorySize, SM_DYN);
    cudaFuncSetAttribute(tc_gemm<3>, cudaFuncAttributeMaxDynamicSharedMemorySize, SM_DYN);

    dim3 tb(32, 8);
    transpose_k<<<dim3(32, 32),   tb>>>(wq, wqT, 1024, 1024);
    transpose_k<<<dim3(32, 32),   tb>>>(wk, wkT, 1024, 1024);
    transpose_k<<<dim3(32, 32),   tb>>>(wv, wvT, 1024, 1024);
    transpose_k<<<dim3(32, 32),   tb>>>(wo, woT, 1024, 1024);
    transpose_k<<<dim3(128, 32),  tb>>>(w1, w1T, 1024, 4096);
    transpose_k<<<dim3(32, 128),  tb>>>(w2, w2T, 4096, 1024);

    dim3 gD(D_MOD / 128, N_TOK / 128);   // (8, 128)
    dim3 gF(FF_D / 128, N_TOK / 128);    // (32, 128)

    tc_gemm<0><<<gD, 256, SM_DYN>>>(x, wqT, nullptr, nullptr, q, D_MOD, D_MOD);
    tc_gemm<0><<<gD, 256, SM_DYN>>>(x, wkT, nullptr, nullptr, k, D_MOD, D_MOD);
    tc_gemm<0><<<gD, 256, SM_DYN>>>(x, wvT, nullptr, nullptr, v, D_MOD, D_MOD);

    phi_kernel<<<2048, 256>>>(q, omega, pq);
    phi_kernel<<<2048, 256>>>(k, omega, pk);

    zero_kernel<<<(64 * M_F * HK + 255) / 256, 256>>>(kv, 64 * M_F * HK);
    zero_kernel<<<(64 * M_F + 255) / 256, 256>>>(z, 64 * M_F);
    kv_kernel<<<256, 256>>>(pk, v, kv, z);

    numden_kernel<<<1024, 256, 70656>>>(pq, kv, z, attn);

    tc_gemm<1><<<gD, 256, SM_DYN>>>(attn, woT, nullptr, x, y, D_MOD, D_MOD);
    ln_kernel<<<N_TOK, 256>>>(y, ln1g, ln1b, x1);

    tc_gemm<2><<<gF, 256, SM_DYN>>>(x1, w1T, b1, nullptr, act, D_MOD, FF_D);
    tc_gemm<3><<<gD, 256, SM_DYN>>>(act, w2T, b2, x1, y, FF_D, D_MOD);
    ln_kernel<<<N_TOK, 256>>>(y, ln2g, ln2b, out);
}